// round 6
// baseline (speedup 1.0000x reference)
#include <cuda_runtime.h>
#include <cuda_bf16.h>
#include <cstdint>
#include <math.h>

#define BSZ   4096
#define NROWS 8192
#define DDIM  256
#define EPSF      1e-8f
#define COS_EPSF  1e-8f
#define INV_SQRT_TAU 1.4142135623730951f   // 1/sqrt(0.5)
#define FP8_SCALE 16.0f                    // zn -> fp8 pre-scale (2^4)
#define OUT_SCALE 0.00390625f              // 2^-8 accumulator post-scale

#define TILE 128
#define OPER_BYTES (TILE * 256)            // 128 rows x 256 fp8 = 32 KB
#define SMEM_BYTES (2 * OPER_BYTES)        // A + B = 64 KB, single stage

// Scratch (device globals; no allocation allowed)
__device__ uint32_t g_zn8[NROWS * 64];     // fp8 e4m3, 4 per word, k-packed
__device__ float g_negsum[NROWS];
__device__ float g_spos[NROWS];

__device__ __forceinline__ uint32_t smem_u32(const void* p) {
    uint32_t a;
    asm("{ .reg .u64 t; cvta.to.shared.u64 t, %1; cvt.u32.u64 %0, t; }"
        : "=r"(a) : "l"(p));
    return a;
}

__device__ __forceinline__ void cp16(uint32_t dst, const void* src) {
    asm volatile("cp.async.cg.shared.global [%0], [%1], 16;"
                 :: "r"(dst), "l"(src) : "memory");
}
#define CP_COMMIT() asm volatile("cp.async.commit_group;" ::: "memory")
#define CP_WAIT0()  asm volatile("cp.async.wait_group 0;" ::: "memory")

#define LDSM_X4(r, a) \
    asm volatile("ldmatrix.sync.aligned.m8n8.x4.shared.b16 {%0,%1,%2,%3}, [%4];" \
        : "=r"((r)[0]), "=r"((r)[1]), "=r"((r)[2]), "=r"((r)[3]) : "r"(a))

// fp8 e4m3 MMA, k32: A 4 regs, B 2 regs, f32 accumulators
#define MMA_FP8(d, a, b0, b1) \
    asm volatile("mma.sync.aligned.m16n8k32.row.col.f32.e4m3.e4m3.f32 " \
        "{%0,%1,%2,%3}, {%4,%5,%6,%7}, {%8,%9}, {%0,%1,%2,%3};" \
        : "+f"((d)[0]), "+f"((d)[1]), "+f"((d)[2]), "+f"((d)[3]) \
        : "r"((a)[0]), "r"((a)[1]), "r"((a)[2]), "r"((a)[3]), "r"(b0), "r"(b1))

// pack 4 floats -> 4 e4m3 bytes, elem0 in byte0 (k-order)
__device__ __forceinline__ uint32_t pack4_e4m3(float e0, float e1, float e2, float e3) {
    uint16_t lo, hi;
    asm("cvt.rn.satfinite.e4m3x2.f32 %0, %1, %2;" : "=h"(lo) : "f"(e1), "f"(e0));
    asm("cvt.rn.satfinite.e4m3x2.f32 %0, %1, %2;" : "=h"(hi) : "f"(e3), "f"(e2));
    return ((uint32_t)hi << 16) | (uint32_t)lo;
}

// ---------------------------------------------------------------------------
// Kernel 1: row-normalize [zi; zj], fold in 1/sqrt(tau) and fp8 pre-scale,
// emit e4m3. One warp per row, no smem/barriers.
// ---------------------------------------------------------------------------
__global__ __launch_bounds__(256) void normalize_kernel(
    const float* __restrict__ zi, const float* __restrict__ zj)
{
    int row = blockIdx.x * 8 + (threadIdx.x >> 5);
    int l = threadIdx.x & 31;
    const float* src = (row < BSZ) ? (zi + (size_t)row * DDIM)
                                   : (zj + (size_t)(row - BSZ) * DDIM);
    float4 v0 = ((const float4*)src)[l];
    float4 v1 = ((const float4*)src)[l + 32];
    float ss = v0.x * v0.x + v0.y * v0.y + v0.z * v0.z + v0.w * v0.w
             + v1.x * v1.x + v1.y * v1.y + v1.z * v1.z + v1.w * v1.w;
    #pragma unroll
    for (int o = 16; o; o >>= 1) ss += __shfl_xor_sync(0xffffffffu, ss, o);
    float scale = (FP8_SCALE * INV_SQRT_TAU) / fmaxf(sqrtf(ss), COS_EPSF);
    uint32_t* dst = g_zn8 + (size_t)row * 64;
    dst[l]      = pack4_e4m3(v0.x * scale, v0.y * scale, v0.z * scale, v0.w * scale);
    dst[l + 32] = pack4_e4m3(v1.x * scale, v1.y * scale, v1.z * scale, v1.w * scale);
    if (l == 0) g_negsum[row] = 0.0f;
}

// ---------------------------------------------------------------------------
// Kernel 2: FP8 HMMA 128x128 tile of sim = zn @ zn^T, upper-triangle only.
// Full K=256 fp8 (256 B/row) in a single smem stage; 8 k-steps of k32.
// 8 warps in 4x2; each warp computes 32x64. ldmatrix.b16 on k-packed fp8
// yields m16n8k32 fragments directly.
// Smem: row r (0..127) * 256B, 16B chunk c (0..15): off = r*256+((c^(r&7))<<4)
// ---------------------------------------------------------------------------
__global__ __launch_bounds__(256, 2) void sim_kernel()
{
    int bi = blockIdx.y, bj = blockIdx.x;
    if (bj < bi) return;                      // symmetry: upper triangle only
    extern __shared__ char smem[];
    int i0 = bi * TILE, j0 = bj * TILE;
    int tid = threadIdx.x, wid = tid >> 5, l = tid & 31;
    int r0 = (wid >> 1) * 32;                 // warp row offset (4 warps)
    int n0 = (wid & 1) * 64;                  // warp col offset (2 warps)
    uint32_t sA = smem_u32(smem);
    uint32_t sB = sA + OPER_BYTES;

    float acc[2][8][4] = {};

    // ldmatrix lane addressing (b16-unit view)
    int a_row = l & 15, a_hi = l >> 4;
    int b_row = (l & 7) + ((l >> 4) << 3), b_hi = (l >> 3) & 1;

    const uint4* gz = (const uint4*)g_zn8;    // 16 uint4 per 256-B row

    // single-stage load: 2048 x 16B per operand, 16 cp.async per thread
    #pragma unroll
    for (int it = 0; it < 8; it++) {
        int f = tid + it * 256;               // 0..2047
        int r = f >> 4, c = f & 15;
        uint32_t off = (uint32_t)(r * 256 + ((c ^ (r & 7)) << 4));
        cp16(sA + off, &gz[(size_t)(i0 + r) * 16 + c]);
        cp16(sB + off, &gz[(size_t)(j0 + r) * 16 + c]);
    }
    CP_COMMIT();
    CP_WAIT0();
    __syncthreads();

    #pragma unroll
    for (int ks = 0; ks < 8; ks++) {          // k32 per step
        uint32_t af[2][4], bf[4][4];
        #pragma unroll
        for (int mt = 0; mt < 2; mt++) {
            int row = r0 + mt * 16 + a_row;
            LDSM_X4(af[mt], sA + row * 256 + (((2 * ks + a_hi) ^ (row & 7)) << 4));
        }
        #pragma unroll
        for (int np = 0; np < 4; np++) {
            int row = n0 + np * 16 + b_row;
            LDSM_X4(bf[np], sB + row * 256 + (((2 * ks + b_hi) ^ (row & 7)) << 4));
        }
        #pragma unroll
        for (int mt = 0; mt < 2; mt++)
            #pragma unroll
            for (int np = 0; np < 4; np++) {
                MMA_FP8(acc[mt][2 * np + 0], af[mt], bf[np][0], bf[np][1]);
                MMA_FP8(acc[mt][2 * np + 1], af[mt], bf[np][2], bf[np][3]);
            }
    }

    // ---- epilogue (accumulators carry 2^8 x logits) ----
    int gid = l >> 2, t4 = l & 3;
    bool offd = (bj != bi);
    float cs0[8] = {}, cs1[8] = {};           // column partial sums

    #pragma unroll
    for (int mt = 0; mt < 2; mt++) {
        int ra = i0 + r0 + mt * 16 + gid;
        int rb = ra + 8;
        int pa = (ra < BSZ) ? ra + BSZ : ra - BSZ;
        int pb = (rb < BSZ) ? rb + BSZ : rb - BSZ;
        float rsa = 0.0f, rsb = 0.0f;
        #pragma unroll
        for (int nt = 0; nt < 8; nt++) {
            int col = j0 + n0 + nt * 8 + 2 * t4;
            float s0 = acc[mt][nt][0] * OUT_SCALE, s1 = acc[mt][nt][1] * OUT_SCALE;
            float s2 = acc[mt][nt][2] * OUT_SCALE, s3 = acc[mt][nt][3] * OUT_SCALE;
            // positive-pair capture: pair offset = BSZ -> always off-diag tile;
            // symmetric value serves both rows, each written once chip-wide.
            if (col == pa)     { g_spos[ra] = s0; g_spos[col] = s0; }
            if (col + 1 == pa) { g_spos[ra] = s1; g_spos[col + 1] = s1; }
            if (col == pb)     { g_spos[rb] = s2; g_spos[col] = s2; }
            if (col + 1 == pb) { g_spos[rb] = s3; g_spos[col + 1] = s3; }
            float e0 = (col == ra)     ? 0.0f : __expf(s0);
            float e1 = (col + 1 == ra) ? 0.0f : __expf(s1);
            float e2 = (col == rb)     ? 0.0f : __expf(s2);
            float e3 = (col + 1 == rb) ? 0.0f : __expf(s3);
            rsa += e0 + e1; rsb += e2 + e3;
            cs0[nt] += e0 + e2; cs1[nt] += e1 + e3;
        }
        rsa += __shfl_xor_sync(0xffffffffu, rsa, 1);
        rsa += __shfl_xor_sync(0xffffffffu, rsa, 2);
        rsb += __shfl_xor_sync(0xffffffffu, rsb, 1);
        rsb += __shfl_xor_sync(0xffffffffu, rsb, 2);
        if (t4 == 0) {
            atomicAdd(&g_negsum[ra], rsa);
            atomicAdd(&g_negsum[rb], rsb);
        }
    }

    if (offd) {
        // transpose contribution: column sums -> rows of the j-block
        #pragma unroll
        for (int nt = 0; nt < 8; nt++) {
            float c0 = cs0[nt], c1 = cs1[nt];
            c0 += __shfl_xor_sync(0xffffffffu, c0, 4);
            c0 += __shfl_xor_sync(0xffffffffu, c0, 8);
            c0 += __shfl_xor_sync(0xffffffffu, c0, 16);
            c1 += __shfl_xor_sync(0xffffffffu, c1, 4);
            c1 += __shfl_xor_sync(0xffffffffu, c1, 8);
            c1 += __shfl_xor_sync(0xffffffffu, c1, 16);
            if (gid == 0) {
                int col = j0 + n0 + nt * 8 + 2 * t4;
                atomicAdd(&g_negsum[col], c0);
                atomicAdd(&g_negsum[col + 1], c1);
            }
        }
    }
}

// ---------------------------------------------------------------------------
// Kernel 3: loss = mean( log(negsum + eps) - s_pos ), one 1024-thread block
// ---------------------------------------------------------------------------
__global__ __launch_bounds__(1024) void loss_kernel(float* __restrict__ out)
{
    __shared__ float sh[32];
    int t = threadIdx.x, l = t & 31, w = t >> 5;
    float acc = 0.0f;
    #pragma unroll
    for (int it = 0; it < 8; it++) {
        int i = t + it * 1024;
        acc += __logf(g_negsum[i] + EPSF) - g_spos[i];
    }
    #pragma unroll
    for (int o = 16; o; o >>= 1) acc += __shfl_xor_sync(0xffffffffu, acc, o);
    if (l == 0) sh[w] = acc;
    __syncthreads();
    if (w == 0) {
        acc = sh[l];
        #pragma unroll
        for (int o = 16; o; o >>= 1) acc += __shfl_xor_sync(0xffffffffu, acc, o);
        if (l == 0) out[0] = acc / (float)NROWS;
    }
}

// ---------------------------------------------------------------------------
extern "C" void kernel_launch(void* const* d_in, const int* in_sizes, int n_in,
                              void* d_out, int out_size)
{
    const float* zi = (const float*)d_in[0];
    const float* zj = (const float*)d_in[1];
    float* out = (float*)d_out;

    static int inited = 0;
    if (!inited) {
        cudaFuncSetAttribute(sim_kernel,
                             cudaFuncAttributeMaxDynamicSharedMemorySize,
                             SMEM_BYTES);
        inited = 1;
    }

    normalize_kernel<<<NROWS / 8, 256>>>(zi, zj);
    dim3 grid(NROWS / TILE, NROWS / TILE);    // 64 x 64, lower triangle exits
    sim_kernel<<<grid, 256, SMEM_BYTES>>>();
    loss_kernel<<<1, 1024>>>(out);
}

// round 7
// speedup vs baseline: 1.0232x; 1.0232x over previous
#include <cuda_runtime.h>
#include <cuda_bf16.h>
#include <cstdint>
#include <math.h>

#define BSZ   4096
#define NROWS 8192
#define DDIM  256
#define EPSF      1e-8f
#define COS_EPSF  1e-8f
#define INV_SQRT_TAU 1.4142135623730951f   // 1/sqrt(0.5)

#define TILE 128
#define NBLK 64                            // 8192 / 128 row-blocks
#define NTILES 2080                        // NBLK*(NBLK+1)/2 upper-tri tiles
#define GRID 296                           // persistent CTAs (2 per SM)
#define STAGE_BYTES (TILE * 128)           // 16 KB per operand per stage (BK=64 bf16)
#define BUF_BYTES (2 * STAGE_BYTES)        // A + B per stage
#define SMEM_BYTES (3 * BUF_BYTES)         // 3-deep ring: 96 KB

// Scratch (device globals; no allocation allowed)
__device__ __nv_bfloat16 g_zn[NROWS * DDIM];   // normalized * 1/sqrt(tau)
__device__ float g_negsum[NROWS];
__device__ float g_spos[NROWS];

__device__ __forceinline__ uint32_t smem_u32(const void* p) {
    uint32_t a;
    asm("{ .reg .u64 t; cvta.to.shared.u64 t, %1; cvt.u32.u64 %0, t; }"
        : "=r"(a) : "l"(p));
    return a;
}
__device__ __forceinline__ void cp16(uint32_t dst, const void* src) {
    asm volatile("cp.async.cg.shared.global [%0], [%1], 16;"
                 :: "r"(dst), "l"(src) : "memory");
}
#define CP_COMMIT() asm volatile("cp.async.commit_group;" ::: "memory")
#define CP_WAIT1()  asm volatile("cp.async.wait_group 1;" ::: "memory")

#define LDSM_X4(r, a) \
    asm volatile("ldmatrix.sync.aligned.m8n8.x4.shared.b16 {%0,%1,%2,%3}, [%4];" \
        : "=r"((r)[0]), "=r"((r)[1]), "=r"((r)[2]), "=r"((r)[3]) : "r"(a))

#define MMA16816(d, a, b0, b1) \
    asm volatile("mma.sync.aligned.m16n8k16.row.col.f32.bf16.bf16.f32 " \
        "{%0,%1,%2,%3}, {%4,%5,%6,%7}, {%8,%9}, {%0,%1,%2,%3};" \
        : "+f"((d)[0]), "+f"((d)[1]), "+f"((d)[2]), "+f"((d)[3]) \
        : "r"((a)[0]), "r"((a)[1]), "r"((a)[2]), "r"((a)[3]), "r"(b0), "r"(b1))

// linear upper-triangle index -> (bi, bj), bi <= bj, NBLK row-blocks
__device__ __forceinline__ void tile_coords(int t, int& bi, int& bj) {
    int b = (int)((2.0f * NBLK + 1.0f
                   - sqrtf((2.0f * NBLK + 1.0f) * (2.0f * NBLK + 1.0f) - 8.0f * t)) * 0.5f);
    while ((b + 1) * (2 * NBLK + 1 - (b + 1)) / 2 <= t) b++;
    while (b * (2 * NBLK + 1 - b) / 2 > t) b--;
    bi = b;
    bj = b + (t - b * (2 * NBLK + 1 - b) / 2);
}

// ---------------------------------------------------------------------------
// Kernel 1: row-normalize [zi; zj], fold in 1/sqrt(tau), emit bf16.
// ---------------------------------------------------------------------------
__global__ __launch_bounds__(256) void normalize_kernel(
    const float* __restrict__ zi, const float* __restrict__ zj)
{
    int row = blockIdx.x * 8 + (threadIdx.x >> 5);
    int l = threadIdx.x & 31;
    const float* src = (row < BSZ) ? (zi + (size_t)row * DDIM)
                                   : (zj + (size_t)(row - BSZ) * DDIM);
    float4 v0 = ((const float4*)src)[l];
    float4 v1 = ((const float4*)src)[l + 32];
    float ss = v0.x * v0.x + v0.y * v0.y + v0.z * v0.z + v0.w * v0.w
             + v1.x * v1.x + v1.y * v1.y + v1.z * v1.z + v1.w * v1.w;
    #pragma unroll
    for (int o = 16; o; o >>= 1) ss += __shfl_xor_sync(0xffffffffu, ss, o);
    float scale = INV_SQRT_TAU / fmaxf(sqrtf(ss), COS_EPSF);
    __nv_bfloat162* dst = (__nv_bfloat162*)(g_zn + (size_t)row * DDIM);
    dst[2 * l + 0]  = __nv_bfloat162(__float2bfloat16(v0.x * scale), __float2bfloat16(v0.y * scale));
    dst[2 * l + 1]  = __nv_bfloat162(__float2bfloat16(v0.z * scale), __float2bfloat16(v0.w * scale));
    dst[64 + 2 * l] = __nv_bfloat162(__float2bfloat16(v1.x * scale), __float2bfloat16(v1.y * scale));
    dst[65 + 2 * l] = __nv_bfloat162(__float2bfloat16(v1.z * scale), __float2bfloat16(v1.w * scale));
    if (l == 0) g_negsum[row] = 0.0f;
}

// ---------------------------------------------------------------------------
// Kernel 2: persistent HMMA tiles of sim = zn @ zn^T (upper triangle).
// 296 CTAs loop over tiles with a continuous 3-stage cp.async ring that
// crosses tile boundaries: next tile's loads stream during this tile's
// epilogue. One __syncthreads per stage.
// Stage layout: row r (0..127) * 128B, chunk c (0..7): off=r*128+((c^(r&7))<<4)
// ---------------------------------------------------------------------------
__global__ __launch_bounds__(256, 2) void sim_kernel()
{
    extern __shared__ char smem[];
    uint32_t sbase = smem_u32(smem);
    int tid = threadIdx.x, wid = tid >> 5, l = tid & 31;
    int r0 = (wid >> 1) * 32;                 // warp row offset (4 warps)
    int n0 = (wid & 1) * 64;                  // warp col offset (2 warps)

    // ldmatrix lane addressing
    int a_row = l & 15, a_hi = l >> 4;
    int b_row = (l & 7) + ((l >> 4) << 3), b_hi = (l >> 3) & 1;

    const uint4* gz = (const uint4*)g_zn;     // 32 uint4 per 256-elem row

    // per-thread load coords (4 x 16B per operand per stage)
    int lr[4], lc[4]; uint32_t loff[4];
    #pragma unroll
    for (int it = 0; it < 4; it++) {
        int f = tid + it * 256;
        lr[it] = f >> 3; lc[it] = f & 7;
        loff[it] = (uint32_t)(lr[it] * 128 + ((lc[it] ^ (lr[it] & 7)) << 4));
    }

    auto issue = [&](int buf, int i0, int j0, int kc) {
        uint32_t b = sbase + (uint32_t)(buf * BUF_BYTES);
        #pragma unroll
        for (int it = 0; it < 4; it++) {
            cp16(b + loff[it],               &gz[(size_t)(i0 + lr[it]) * 32 + kc * 8 + lc[it]]);
            cp16(b + STAGE_BYTES + loff[it], &gz[(size_t)(j0 + lr[it]) * 32 + kc * 8 + lc[it]]);
        }
    };

    int t = blockIdx.x;
    int bi, bj; tile_coords(t, bi, bj);
    int i0 = bi * TILE, j0 = bj * TILE;
    int nbi = 0, nbj = 0, ni0 = 0, nj0 = 0;
    bool has_next = (t + GRID) < NTILES;
    if (has_next) { tile_coords(t + GRID, nbi, nbj); ni0 = nbi * TILE; nj0 = nbj * TILE; }

    // prologue: first tile's stages 0,1 into buffers 0,1
    issue(0, i0, j0, 0); CP_COMMIT();
    issue(1, i0, j0, 1); CP_COMMIT();
    int g = 0;                                // global stage counter

    while (true) {
        float acc[2][8][4] = {};

        #pragma unroll
        for (int kc = 0; kc < 4; kc++) {
            CP_WAIT1();                       // stage g arrived (<=1 newer pending)
            __syncthreads();                  // all warps done with buf (g+2)%3
            // issue stage g+2 (this tile kc+2, or next tile kc-2)
            int ib = (g + 2) % 3;
            if (kc < 2)            issue(ib, i0, j0, kc + 2);
            else if (has_next)     issue(ib, ni0, nj0, kc - 2);
            CP_COMMIT();                      // always commit (keeps group count aligned)

            uint32_t sA = sbase + (uint32_t)((g % 3) * BUF_BYTES);
            uint32_t sB = sA + STAGE_BYTES;
            #pragma unroll
            for (int ks = 0; ks < 4; ks++) {
                uint32_t af[2][4], bf[4][4];
                #pragma unroll
                for (int mt = 0; mt < 2; mt++) {
                    int row = r0 + mt * 16 + a_row;
                    LDSM_X4(af[mt], sA + row * 128 + (((2 * ks + a_hi) ^ (row & 7)) << 4));
                }
                #pragma unroll
                for (int np = 0; np < 4; np++) {
                    int row = n0 + np * 16 + b_row;
                    LDSM_X4(bf[np], sB + row * 128 + (((2 * ks + b_hi) ^ (row & 7)) << 4));
                }
                #pragma unroll
                for (int mt = 0; mt < 2; mt++)
                    #pragma unroll
                    for (int np = 0; np < 4; np++) {
                        MMA16816(acc[mt][2 * np + 0], af[mt], bf[np][0], bf[np][1]);
                        MMA16816(acc[mt][2 * np + 1], af[mt], bf[np][2], bf[np][3]);
                    }
            }
            g++;
        }

        // ---- epilogue (register-only inputs; overlaps next tile's loads) ----
        int gid = l >> 2, t4 = l & 3;
        bool offd = (bj != bi);
        float cs0[8] = {}, cs1[8] = {};

        #pragma unroll
        for (int mt = 0; mt < 2; mt++) {
            int ra = i0 + r0 + mt * 16 + gid;
            int rb = ra + 8;
            int pa = (ra < BSZ) ? ra + BSZ : ra - BSZ;
            int pb = (rb < BSZ) ? rb + BSZ : rb - BSZ;
            float rsa = 0.0f, rsb = 0.0f;
            #pragma unroll
            for (int nt = 0; nt < 8; nt++) {
                int col = j0 + n0 + nt * 8 + 2 * t4;
                float s0 = acc[mt][nt][0], s1 = acc[mt][nt][1];
                float s2 = acc[mt][nt][2], s3 = acc[mt][nt][3];
                if (col == pa)     { g_spos[ra] = s0; g_spos[col] = s0; }
                if (col + 1 == pa) { g_spos[ra] = s1; g_spos[col + 1] = s1; }
                if (col == pb)     { g_spos[rb] = s2; g_spos[col] = s2; }
                if (col + 1 == pb) { g_spos[rb] = s3; g_spos[col + 1] = s3; }
                float e0 = (col == ra)     ? 0.0f : __expf(s0);
                float e1 = (col + 1 == ra) ? 0.0f : __expf(s1);
                float e2 = (col == rb)     ? 0.0f : __expf(s2);
                float e3 = (col + 1 == rb) ? 0.0f : __expf(s3);
                rsa += e0 + e1; rsb += e2 + e3;
                cs0[nt] += e0 + e2; cs1[nt] += e1 + e3;
            }
            rsa += __shfl_xor_sync(0xffffffffu, rsa, 1);
            rsa += __shfl_xor_sync(0xffffffffu, rsa, 2);
            rsb += __shfl_xor_sync(0xffffffffu, rsb, 1);
            rsb += __shfl_xor_sync(0xffffffffu, rsb, 2);
            if (t4 == 0) {
                atomicAdd(&g_negsum[ra], rsa);
                atomicAdd(&g_negsum[rb], rsb);
            }
        }
        if (offd) {
            #pragma unroll
            for (int nt = 0; nt < 8; nt++) {
                float c0 = cs0[nt], c1 = cs1[nt];
                c0 += __shfl_xor_sync(0xffffffffu, c0, 4);
                c0 += __shfl_xor_sync(0xffffffffu, c0, 8);
                c0 += __shfl_xor_sync(0xffffffffu, c0, 16);
                c1 += __shfl_xor_sync(0xffffffffu, c1, 4);
                c1 += __shfl_xor_sync(0xffffffffu, c1, 8);
                c1 += __shfl_xor_sync(0xffffffffu, c1, 16);
                if (gid == 0) {
                    int col = j0 + n0 + nt * 8 + 2 * t4;
                    atomicAdd(&g_negsum[col], c0);
                    atomicAdd(&g_negsum[col + 1], c1);
                }
            }
        }

        t += GRID;
        if (t >= NTILES) break;
        bi = nbi; bj = nbj; i0 = ni0; j0 = nj0;
        has_next = (t + GRID) < NTILES;
        if (has_next) { tile_coords(t + GRID, nbi, nbj); ni0 = nbi * TILE; nj0 = nbj * TILE; }
    }
}

// ---------------------------------------------------------------------------
// Kernel 3: loss = mean( log(negsum + eps) - s_pos )
// ---------------------------------------------------------------------------
__global__ __launch_bounds__(1024) void loss_kernel(float* __restrict__ out)
{
    __shared__ float sh[32];
    int t = threadIdx.x, l = t & 31, w = t >> 5;
    float acc = 0.0f;
    #pragma unroll
    for (int it = 0; it < 8; it++) {
        int i = t + it * 1024;
        acc += __logf(g_negsum[i] + EPSF) - g_spos[i];
    }
    #pragma unroll
    for (int o = 16; o; o >>= 1) acc += __shfl_xor_sync(0xffffffffu, acc, o);
    if (l == 0) sh[w] = acc;
    __syncthreads();
    if (w == 0) {
        acc = sh[l];
        #pragma unroll
        for (int o = 16; o; o >>= 1) acc += __shfl_xor_sync(0xffffffffu, acc, o);
        if (l == 0) out[0] = acc / (float)NROWS;
    }
}

// ---------------------------------------------------------------------------
extern "C" void kernel_launch(void* const* d_in, const int* in_sizes, int n_in,
                              void* d_out, int out_size)
{
    const float* zi = (const float*)d_in[0];
    const float* zj = (const float*)d_in[1];
    float* out = (float*)d_out;

    static int inited = 0;
    if (!inited) {
        cudaFuncSetAttribute(sim_kernel,
                             cudaFuncAttributeMaxDynamicSharedMemorySize,
                             SMEM_BYTES);
        inited = 1;
    }

    normalize_kernel<<<NROWS / 8, 256>>>(zi, zj);
    sim_kernel<<<GRID, 256, SMEM_BYTES>>>();
    loss_kernel<<<1, 1024>>>(out);
}

// round 8
// speedup vs baseline: 1.0583x; 1.0343x over previous
#include <cuda_runtime.h>
#include <cuda_bf16.h>
#include <cstdint>
#include <math.h>

#define BSZ   4096
#define NROWS 8192
#define DDIM  256
#define EPSF      1e-8f
#define COS_EPSF  1e-8f
#define INV_SQRT_TAU 1.4142135623730951f   // 1/sqrt(0.5)
#define FP8_SCALE 16.0f                    // zn -> fp8 pre-scale (2^4)
#define OUT_SCALE 0.00390625f              // 2^-8 accumulator post-scale

#define TILE 128
#define NBLK 64                            // 8192 / 128 row-blocks
#define NTILES 2080                        // NBLK*(NBLK+1)/2 upper-tri tiles
#define STAGE_BYTES (TILE * 128)           // 128 rows x 128 B (BK=128 fp8) = 16 KB
#define SMEM_BYTES (4 * STAGE_BYTES)       // A0,B0,A1,B1 = 64 KB

// Scratch (device globals; no allocation allowed)
__device__ uint32_t g_zn8[NROWS * 64];     // e4m3, 4/word, k-packed (256 B/row)
__device__ float g_negsum[NROWS];
__device__ float g_spos[NROWS];

__device__ __forceinline__ uint32_t smem_u32(const void* p) {
    uint32_t a;
    asm("{ .reg .u64 t; cvta.to.shared.u64 t, %1; cvt.u32.u64 %0, t; }"
        : "=r"(a) : "l"(p));
    return a;
}
__device__ __forceinline__ void cp16(uint32_t dst, const void* src) {
    asm volatile("cp.async.cg.shared.global [%0], [%1], 16;"
                 :: "r"(dst), "l"(src) : "memory");
}
#define CP_COMMIT() asm volatile("cp.async.commit_group;" ::: "memory")
#define CP_WAIT0()  asm volatile("cp.async.wait_group 0;" ::: "memory")

#define LDSM_X4(r, a) \
    asm volatile("ldmatrix.sync.aligned.m8n8.x4.shared.b16 {%0,%1,%2,%3}, [%4];" \
        : "=r"((r)[0]), "=r"((r)[1]), "=r"((r)[2]), "=r"((r)[3]) : "r"(a))

// fp8 e4m3 MMA, k32: A 4 regs, B 2 regs, f32 accumulators
#define MMA_FP8(d, a, b0, b1) \
    asm volatile("mma.sync.aligned.m16n8k32.row.col.f32.e4m3.e4m3.f32 " \
        "{%0,%1,%2,%3}, {%4,%5,%6,%7}, {%8,%9}, {%0,%1,%2,%3};" \
        : "+f"((d)[0]), "+f"((d)[1]), "+f"((d)[2]), "+f"((d)[3]) \
        : "r"((a)[0]), "r"((a)[1]), "r"((a)[2]), "r"((a)[3]), "r"(b0), "r"(b1))

// pack 4 floats -> 4 e4m3 bytes, elem0 in byte0 (k-order)
__device__ __forceinline__ uint32_t pack4_e4m3(float e0, float e1, float e2, float e3) {
    uint16_t lo, hi;
    asm("cvt.rn.satfinite.e4m3x2.f32 %0, %1, %2;" : "=h"(lo) : "f"(e1), "f"(e0));
    asm("cvt.rn.satfinite.e4m3x2.f32 %0, %1, %2;" : "=h"(hi) : "f"(e3), "f"(e2));
    return ((uint32_t)hi << 16) | (uint32_t)lo;
}

// linear upper-triangle index -> (bi, bj), bi <= bj
__device__ __forceinline__ void tile_coords(int t, int& bi, int& bj) {
    int b = (int)((2.0f * NBLK + 1.0f
                   - sqrtf((2.0f * NBLK + 1.0f) * (2.0f * NBLK + 1.0f) - 8.0f * t)) * 0.5f);
    while ((b + 1) * (2 * NBLK + 1 - (b + 1)) / 2 <= t) b++;
    while (b * (2 * NBLK + 1 - b) / 2 > t) b--;
    bi = b;
    bj = b + (t - b * (2 * NBLK + 1 - b) / 2);
}

// ---------------------------------------------------------------------------
// Kernel 1: row-normalize [zi; zj], fold in 1/sqrt(tau) + fp8 pre-scale,
// emit e4m3. One warp per row, no smem/barriers.
// ---------------------------------------------------------------------------
__global__ __launch_bounds__(256) void normalize_kernel(
    const float* __restrict__ zi, const float* __restrict__ zj)
{
    int row = blockIdx.x * 8 + (threadIdx.x >> 5);
    int l = threadIdx.x & 31;
    const float* src = (row < BSZ) ? (zi + (size_t)row * DDIM)
                                   : (zj + (size_t)(row - BSZ) * DDIM);
    float4 v0 = ((const float4*)src)[l];
    float4 v1 = ((const float4*)src)[l + 32];
    float ss = v0.x * v0.x + v0.y * v0.y + v0.z * v0.z + v0.w * v0.w
             + v1.x * v1.x + v1.y * v1.y + v1.z * v1.z + v1.w * v1.w;
    #pragma unroll
    for (int o = 16; o; o >>= 1) ss += __shfl_xor_sync(0xffffffffu, ss, o);
    float scale = (FP8_SCALE * INV_SQRT_TAU) / fmaxf(sqrtf(ss), COS_EPSF);
    uint32_t* dst = g_zn8 + (size_t)row * 64;
    dst[l]      = pack4_e4m3(v0.x * scale, v0.y * scale, v0.z * scale, v0.w * scale);
    dst[l + 32] = pack4_e4m3(v1.x * scale, v1.y * scale, v1.z * scale, v1.w * scale);
    if (l == 0) g_negsum[row] = 0.0f;
}

// ---------------------------------------------------------------------------
// Kernel 2: FP8 HMMA 128x128 tile of sim = zn @ zn^T, 1D triangular grid
// (2080 CTAs), cp.async double-buffered over 2 k-stages of BK=128.
// 8 warps in 4x2; each warp computes 32x64 via m16n8k32 e4m3 mma.sync.
// Stage layout: row r (0..127) * 128B, 16B chunk c (0..7), XOR swizzle.
// ---------------------------------------------------------------------------
__global__ __launch_bounds__(256, 2) void sim_kernel()
{
    int bi, bj;
    tile_coords((int)blockIdx.x, bi, bj);
    extern __shared__ char smem[];
    int i0 = bi * TILE, j0 = bj * TILE;
    int tid = threadIdx.x, wid = tid >> 5, l = tid & 31;
    int r0 = (wid >> 1) * 32;                 // warp row offset (4 warps)
    int n0 = (wid & 1) * 64;                  // warp col offset (2 warps)
    uint32_t sbase = smem_u32(smem);

    float acc[2][8][4] = {};

    // ldmatrix lane addressing (b16-unit view of k-packed fp8)
    int a_row = l & 15, a_hi = l >> 4;
    int b_row = (l & 7) + ((l >> 4) << 3), b_hi = (l >> 3) & 1;

    const uint4* gz = (const uint4*)g_zn8;    // 16 uint4 per 256-B row

    // per-thread load coords (4 x 16B per operand per stage)
    int lr[4], lc[4]; uint32_t loff[4];
    #pragma unroll
    for (int it = 0; it < 4; it++) {
        int f = tid + it * 256;               // 0..1023
        lr[it] = f >> 3; lc[it] = f & 7;
        loff[it] = (uint32_t)(lr[it] * 128 + ((lc[it] ^ (lr[it] & 7)) << 4));
    }

    // prologue: stage 0 (K bytes 0..127) into buffer 0
    #pragma unroll
    for (int it = 0; it < 4; it++) {
        cp16(sbase + loff[it],               &gz[(size_t)(i0 + lr[it]) * 16 + lc[it]]);
        cp16(sbase + STAGE_BYTES + loff[it], &gz[(size_t)(j0 + lr[it]) * 16 + lc[it]]);
    }
    CP_COMMIT();

    #pragma unroll
    for (int kc = 0; kc < 2; kc++) {
        CP_WAIT0();
        __syncthreads();
        if (kc == 0) {                        // prefetch stage 1 into buffer 1
            uint32_t nb = sbase + 2 * STAGE_BYTES;
            #pragma unroll
            for (int it = 0; it < 4; it++) {
                cp16(nb + loff[it],               &gz[(size_t)(i0 + lr[it]) * 16 + 8 + lc[it]]);
                cp16(nb + STAGE_BYTES + loff[it], &gz[(size_t)(j0 + lr[it]) * 16 + 8 + lc[it]]);
            }
            CP_COMMIT();
        }
        uint32_t sA = sbase + (uint32_t)(kc * 2 * STAGE_BYTES);
        uint32_t sB = sA + STAGE_BYTES;

        #pragma unroll
        for (int ks = 0; ks < 4; ks++) {      // k32 per step
            uint32_t af[2][4], bf[4][4];
            #pragma unroll
            for (int mt = 0; mt < 2; mt++) {
                int row = r0 + mt * 16 + a_row;
                LDSM_X4(af[mt], sA + row * 128 + (((2 * ks + a_hi) ^ (row & 7)) << 4));
            }
            #pragma unroll
            for (int np = 0; np < 4; np++) {
                int row = n0 + np * 16 + b_row;
                LDSM_X4(bf[np], sB + row * 128 + (((2 * ks + b_hi) ^ (row & 7)) << 4));
            }
            #pragma unroll
            for (int mt = 0; mt < 2; mt++)
                #pragma unroll
                for (int np = 0; np < 4; np++) {
                    MMA_FP8(acc[mt][2 * np + 0], af[mt], bf[np][0], bf[np][1]);
                    MMA_FP8(acc[mt][2 * np + 1], af[mt], bf[np][2], bf[np][3]);
                }
        }
        if (kc == 0) __syncthreads();         // reads done before any reuse
    }

    // ---- epilogue (accumulators carry 2^8 x logits) ----
    int gid = l >> 2, t4 = l & 3;
    bool offd = (bj != bi);
    float cs0[8] = {}, cs1[8] = {};           // column partial sums

    #pragma unroll
    for (int mt = 0; mt < 2; mt++) {
        int ra = i0 + r0 + mt * 16 + gid;
        int rb = ra + 8;
        int pa = (ra < BSZ) ? ra + BSZ : ra - BSZ;
        int pb = (rb < BSZ) ? rb + BSZ : rb - BSZ;
        float rsa = 0.0f, rsb = 0.0f;
        #pragma unroll
        for (int nt = 0; nt < 8; nt++) {
            int col = j0 + n0 + nt * 8 + 2 * t4;
            float s0 = acc[mt][nt][0] * OUT_SCALE, s1 = acc[mt][nt][1] * OUT_SCALE;
            float s2 = acc[mt][nt][2] * OUT_SCALE, s3 = acc[mt][nt][3] * OUT_SCALE;
            // positive-pair capture: pair offset = BSZ -> always off-diag tile;
            // symmetric value serves both rows, each written once chip-wide.
            if (col == pa)     { g_spos[ra] = s0; g_spos[col] = s0; }
            if (col + 1 == pa) { g_spos[ra] = s1; g_spos[col + 1] = s1; }
            if (col == pb)     { g_spos[rb] = s2; g_spos[col] = s2; }
            if (col + 1 == pb) { g_spos[rb] = s3; g_spos[col + 1] = s3; }
            float e0 = (col == ra)     ? 0.0f : __expf(s0);
            float e1 = (col + 1 == ra) ? 0.0f : __expf(s1);
            float e2 = (col == rb)     ? 0.0f : __expf(s2);
            float e3 = (col + 1 == rb) ? 0.0f : __expf(s3);
            rsa += e0 + e1; rsb += e2 + e3;
            cs0[nt] += e0 + e2; cs1[nt] += e1 + e3;
        }
        rsa += __shfl_xor_sync(0xffffffffu, rsa, 1);
        rsa += __shfl_xor_sync(0xffffffffu, rsa, 2);
        rsb += __shfl_xor_sync(0xffffffffu, rsb, 1);
        rsb += __shfl_xor_sync(0xffffffffu, rsb, 2);
        if (t4 == 0) {
            atomicAdd(&g_negsum[ra], rsa);
            atomicAdd(&g_negsum[rb], rsb);
        }
    }

    if (offd) {
        // transpose contribution: column sums -> rows of the j-block
        #pragma unroll
        for (int nt = 0; nt < 8; nt++) {
            float c0 = cs0[nt], c1 = cs1[nt];
            c0 += __shfl_xor_sync(0xffffffffu, c0, 4);
            c0 += __shfl_xor_sync(0xffffffffu, c0, 8);
            c0 += __shfl_xor_sync(0xffffffffu, c0, 16);
            c1 += __shfl_xor_sync(0xffffffffu, c1, 4);
            c1 += __shfl_xor_sync(0xffffffffu, c1, 8);
            c1 += __shfl_xor_sync(0xffffffffu, c1, 16);
            if (gid == 0) {
                int col = j0 + n0 + nt * 8 + 2 * t4;
                atomicAdd(&g_negsum[col], c0);
                atomicAdd(&g_negsum[col + 1], c1);
            }
        }
    }
}

// ---------------------------------------------------------------------------
// Kernel 3: loss = mean( log(negsum + eps) - s_pos )
// ---------------------------------------------------------------------------
__global__ __launch_bounds__(1024) void loss_kernel(float* __restrict__ out)
{
    __shared__ float sh[32];
    int t = threadIdx.x, l = t & 31, w = t >> 5;
    float acc = 0.0f;
    #pragma unroll
    for (int it = 0; it < 8; it++) {
        int i = t + it * 1024;
        acc += __logf(g_negsum[i] + EPSF) - g_spos[i];
    }
    #pragma unroll
    for (int o = 16; o; o >>= 1) acc += __shfl_xor_sync(0xffffffffu, acc, o);
    if (l == 0) sh[w] = acc;
    __syncthreads();
    if (w == 0) {
        acc = sh[l];
        #pragma unroll
        for (int o = 16; o; o >>= 1) acc += __shfl_xor_sync(0xffffffffu, acc, o);
        if (l == 0) out[0] = acc / (float)NROWS;
    }
}

// ---------------------------------------------------------------------------
extern "C" void kernel_launch(void* const* d_in, const int* in_sizes, int n_in,
                              void* d_out, int out_size)
{
    const float* zi = (const float*)d_in[0];
    const float* zj = (const float*)d_in[1];
    float* out = (float*)d_out;

    static int inited = 0;
    if (!inited) {
        cudaFuncSetAttribute(sim_kernel,
                             cudaFuncAttributeMaxDynamicSharedMemorySize,
                             SMEM_BYTES);
        inited = 1;
    }

    normalize_kernel<<<NROWS / 8, 256>>>(zi, zj);
    sim_kernel<<<NTILES, 256, SMEM_BYTES>>>();
    loss_kernel<<<1, 1024>>>(out);
}